// round 1
// baseline (speedup 1.0000x reference)
#include <cuda_runtime.h>
#include <cstdint>

// GPTQ int4 dequant + GEMM baseline (fp32, shared-memory tiled, 8x8 register tile).
// out[M,N] = x[M,K] @ W[N,K]^T + bias,  W = (nibble - zero[g]) * scale[g], g = k / 128.
//
// M = 8192 (tokens), N = 11008 (out features), K = 4096 (in features), GS = 128.
// qweight: [N, K/2] int32, each int32 holds ONE byte: low nibble = even k, high = odd k.

#define BM 128
#define BN 128
#define BK 32
#define TM 8
#define TN 8
#define NTHREADS 256   // (BM/TM) * (BN/TN) = 16*16

__global__ __launch_bounds__(NTHREADS, 2)
void gptq_gemm_kernel(const float* __restrict__ x,      // [M, K]
                      const int*   __restrict__ qw,     // [N, K/2]
                      const float* __restrict__ scales, // [N, G]
                      const float* __restrict__ zeros,  // [N, G]
                      const float* __restrict__ bias,   // [N]
                      float* __restrict__ out,          // [M, N]
                      int M, int N, int K)
{
    __shared__ float As[BK][BM];   // transposed A tile: As[k][m]
    __shared__ float Bs[BK][BN];   // dequantized W tile: Bs[k][n]

    const int G = K >> 7;          // number of quant groups (GS = 128)

    const int bn = blockIdx.x * BN;
    const int bm = blockIdx.y * BM;
    const int tid = threadIdx.x;

    const int tx = tid & 15;       // n-direction thread coord (0..15)
    const int ty = tid >> 4;       // m-direction thread coord (0..15)

    float acc[TM][TN];
    #pragma unroll
    for (int i = 0; i < TM; i++)
        #pragma unroll
        for (int j = 0; j < TN; j++)
            acc[i][j] = 0.0f;

    // B-load assignment: each thread owns half a row's K-chunk.
    const int b_row  = tid >> 1;          // 0..127  (local n)
    const int b_half = tid & 1;           // which 8 int32s (16 k-values)
    const int gn = bn + b_row;            // global n for this thread's B loads

    for (int k0 = 0; k0 < K; k0 += BK) {
        // ---- Load A tile (128 x 32 fp32), store transposed into As[k][m] ----
        // 1024 float4 loads total, 4 per thread.
        #pragma unroll
        for (int i = 0; i < 4; i++) {
            int f   = tid + i * NTHREADS;
            int row = f >> 3;              // 0..127
            int c4  = f & 7;               // 0..7 (float4 index within the 32-col chunk)
            float4 v = *reinterpret_cast<const float4*>(
                x + (size_t)(bm + row) * K + k0 + c4 * 4);
            As[c4 * 4 + 0][row] = v.x;
            As[c4 * 4 + 1][row] = v.y;
            As[c4 * 4 + 2][row] = v.z;
            As[c4 * 4 + 3][row] = v.w;
        }

        // ---- Load + dequant B tile (128 rows x 32 k) into Bs[k][n] ----
        // BK=32 lies fully inside one quant group (GS=128), so one scale/zero per row.
        {
            const int g  = k0 >> 7;
            const float sc = scales[(size_t)gn * G + g];
            const float zp = zeros [(size_t)gn * G + g];
            const int* qrow = qw + (size_t)gn * (K >> 1) + (k0 >> 1) + b_half * 8;
            int4 q0 = *reinterpret_cast<const int4*>(qrow);
            int4 q1 = *reinterpret_cast<const int4*>(qrow + 4);
            int qs[8] = {q0.x, q0.y, q0.z, q0.w, q1.x, q1.y, q1.z, q1.w};
            #pragma unroll
            for (int j = 0; j < 8; j++) {
                int b  = qs[j];                       // one byte
                int kk = b_half * 16 + j * 2;         // k offset inside tile
                float lo = (float)(b & 15);           // even k
                float hi = (float)((b >> 4) & 15);    // odd k
                Bs[kk    ][b_row] = (lo - zp) * sc;
                Bs[kk + 1][b_row] = (hi - zp) * sc;
            }
        }

        __syncthreads();

        // ---- Compute: 8x8 register tile per thread ----
        #pragma unroll
        for (int k = 0; k < BK; k++) {
            float a_frag[TM], b_frag[TN];
            #pragma unroll
            for (int i = 0; i < TM; i += 4) {
                float4 v = *reinterpret_cast<const float4*>(&As[k][ty * TM + i]);
                a_frag[i] = v.x; a_frag[i+1] = v.y; a_frag[i+2] = v.z; a_frag[i+3] = v.w;
            }
            #pragma unroll
            for (int j = 0; j < TN; j += 4) {
                float4 v = *reinterpret_cast<const float4*>(&Bs[k][tx * TN + j]);
                b_frag[j] = v.x; b_frag[j+1] = v.y; b_frag[j+2] = v.z; b_frag[j+3] = v.w;
            }
            #pragma unroll
            for (int i = 0; i < TM; i++)
                #pragma unroll
                for (int j = 0; j < TN; j++)
                    acc[i][j] += a_frag[i] * b_frag[j];
        }

        __syncthreads();
    }

    // ---- Epilogue: add bias, write 8x8 tile (float4 stores) ----
    float bfrag[TN];
    #pragma unroll
    for (int j = 0; j < TN; j += 4) {
        float4 v = *reinterpret_cast<const float4*>(bias + bn + tx * TN + j);
        bfrag[j] = v.x; bfrag[j+1] = v.y; bfrag[j+2] = v.z; bfrag[j+3] = v.w;
    }
    #pragma unroll
    for (int i = 0; i < TM; i++) {
        int m = bm + ty * TM + i;
        #pragma unroll
        for (int j = 0; j < TN; j += 4) {
            int n = bn + tx * TN + j;
            float4 r;
            r.x = acc[i][j    ] + bfrag[j    ];
            r.y = acc[i][j + 1] + bfrag[j + 1];
            r.z = acc[i][j + 2] + bfrag[j + 2];
            r.w = acc[i][j + 3] + bfrag[j + 3];
            *reinterpret_cast<float4*>(out + (size_t)m * N + n) = r;
        }
    }
}

extern "C" void kernel_launch(void* const* d_in, const int* in_sizes, int n_in,
                              void* d_out, int out_size)
{
    const float* x      = (const float*)d_in[0];  // [8192, 4096]
    const int*   qw     = (const int*)  d_in[1];  // [11008, 2048]
    const float* scales = (const float*)d_in[2];  // [11008, 32]
    const float* zeros  = (const float*)d_in[3];  // [11008, 32]
    const float* bias   = (const float*)d_in[4];  // [11008]
    float* out          = (float*)d_out;          // [8192, 11008]

    const int M = 8192, N = 11008, K = 4096;

    dim3 grid(N / BN, M / BM);   // (86, 64)
    dim3 block(NTHREADS);
    gptq_gemm_kernel<<<grid, block>>>(x, qw, scales, zeros, bias, out, M, N, K);
}

// round 4
// speedup vs baseline: 6.7726x; 6.7726x over previous
#include <cuda_runtime.h>
#include <cuda_fp16.h>
#include <cstdint>

// GPTQ int4 linear on GB300 via legacy tensor path (mma.sync, base sm_103 target):
//   Pass 1: dequant qweight -> fp16 W[N,K] (device global), convert x -> fp16.
//   Pass 2: 128x128x64 tiled fp16 GEMM, mma.sync.m16n8k16, ldmatrix, 3-stage cp.async.
// M=8192, N=11008, K=4096, GS=128.

#define M_DIM 8192
#define N_DIM 11008
#define K_DIM 4096
#define BM 128
#define BN 128
#define BK 64                 // halfs per stage = 128 bytes per row (SW128)
#define STAGES 3
#define NITER (K_DIM / BK)    // 64
#define THREADS 256

__device__ __half g_Wh[(size_t)N_DIM * K_DIM];   // 90 MB
__device__ __half g_Xh[(size_t)M_DIM * K_DIM];   // 64 MB

#define SWZ128(o) ((o) ^ (((o) >> 3) & 0x70))

#define CP_ASYNC16(dst, src) \
    asm volatile("cp.async.cg.shared.global [%0], [%1], 16;" :: "r"(dst), "l"(src))
#define CP_COMMIT() asm volatile("cp.async.commit_group;" ::: "memory")
#define CP_WAIT(n)  asm volatile("cp.async.wait_group %0;" :: "n"(n) : "memory")

__device__ __forceinline__ uint32_t smem_u32(const void* p) {
    uint32_t a;
    asm("{ .reg .u64 t; cvta.to.shared.u64 t, %1; cvt.u32.u64 %0, t; }" : "=r"(a) : "l"(p));
    return a;
}
__device__ __forceinline__ void ldsm_x4(uint32_t* r, uint32_t addr) {
    asm volatile("ldmatrix.sync.aligned.m8n8.x4.shared.b16 {%0,%1,%2,%3}, [%4];"
                 : "=r"(r[0]), "=r"(r[1]), "=r"(r[2]), "=r"(r[3]) : "r"(addr));
}
__device__ __forceinline__ void mma16816(float* c, const uint32_t* a, uint32_t b0, uint32_t b1) {
    asm volatile("mma.sync.aligned.m16n8k16.row.col.f32.f16.f16.f32 "
                 "{%0,%1,%2,%3}, {%4,%5,%6,%7}, {%8,%9}, {%0,%1,%2,%3};"
                 : "+f"(c[0]), "+f"(c[1]), "+f"(c[2]), "+f"(c[3])
                 : "r"(a[0]), "r"(a[1]), "r"(a[2]), "r"(a[3]), "r"(b0), "r"(b1));
}

// ---------------- Pass 1: dequant W -> fp16 ----------------
__global__ void dequant_w_kernel(const int* __restrict__ qw,       // [N, K/2], one byte per int32
                                 const float* __restrict__ scales,  // [N, 32]
                                 const float* __restrict__ zeros)   // [N, 32]
{
    size_t t = (size_t)blockIdx.x * blockDim.x + threadIdx.x;   // 1 thread = 4 int32 = 8 weights
    const size_t total = (size_t)N_DIM * (K_DIM / 8);
    if (t >= total) return;
    int n  = (int)(t >> 9);           // K/8 = 512 per row
    int c4 = (int)(t & 511);
    int g  = c4 >> 4;                 // (c4*8)/128
    float sc = scales[(size_t)n * 32 + g];
    float zp = zeros [(size_t)n * 32 + g];
    int4 q = *reinterpret_cast<const int4*>(qw + (size_t)n * 2048 + c4 * 4);
    int qs[4] = {q.x, q.y, q.z, q.w};
    __half h[8];
    #pragma unroll
    for (int j = 0; j < 4; j++) {
        float lo = (float)(qs[j] & 15);
        float hi = (float)((qs[j] >> 4) & 15);
        h[2 * j    ] = __float2half_rn((lo - zp) * sc);
        h[2 * j + 1] = __float2half_rn((hi - zp) * sc);
    }
    *reinterpret_cast<uint4*>(&g_Wh[(size_t)n * K_DIM + (size_t)c4 * 8]) =
        *reinterpret_cast<const uint4*>(h);
}

// ---------------- Pass 1b: convert x -> fp16 ----------------
__global__ void convert_x_kernel(const float* __restrict__ x)
{
    size_t t = (size_t)blockIdx.x * blockDim.x + threadIdx.x;   // 1 thread = 8 floats
    const size_t total = (size_t)M_DIM * K_DIM / 8;
    if (t >= total) return;
    size_t base = t * 8;
    float4 a = *reinterpret_cast<const float4*>(x + base);
    float4 b = *reinterpret_cast<const float4*>(x + base + 4);
    __half h[8] = {__float2half_rn(a.x), __float2half_rn(a.y), __float2half_rn(a.z), __float2half_rn(a.w),
                   __float2half_rn(b.x), __float2half_rn(b.y), __float2half_rn(b.z), __float2half_rn(b.w)};
    *reinterpret_cast<uint4*>(&g_Xh[base]) = *reinterpret_cast<const uint4*>(h);
}

// ---------------- Pass 2: mma.sync fp16 GEMM ----------------
// SMEM per stage: A 128x64 fp16 (16KB) + B 128x64 fp16 (16KB). 3 stages = 96KB.
#define STAGE_BYTES 32768
#define SMEM_TOTAL (STAGES * STAGE_BYTES)

__device__ __forceinline__ void load_stage(uint32_t sA, uint32_t sB,
                                           int bm, int bn, int k0, int tid)
{
    // 1024 16B-chunks per tile, 256 threads -> 4 chunks each per tile.
    #pragma unroll
    for (int j = 0; j < 4; j++) {
        int chunk = tid + j * THREADS;
        int row = chunk >> 3, c16 = chunk & 7;
        uint32_t off = SWZ128((uint32_t)(row * 128 + c16 * 16));
        CP_ASYNC16(sA + off, g_Xh + (size_t)(bm + row) * K_DIM + k0 + c16 * 8);
    }
    #pragma unroll
    for (int j = 0; j < 4; j++) {
        int chunk = tid + j * THREADS;
        int row = chunk >> 3, c16 = chunk & 7;
        uint32_t off = SWZ128((uint32_t)(row * 128 + c16 * 16));
        CP_ASYNC16(sB + off, g_Wh + (size_t)(bn + row) * K_DIM + k0 + c16 * 8);
    }
}

__global__ __launch_bounds__(THREADS, 1)
void gemm_f16_kernel(const float* __restrict__ bias, float* __restrict__ out)
{
    extern __shared__ char smem[];
    const uint32_t sb = smem_u32(smem);
    const int tid = threadIdx.x;
    const int wid = tid >> 5, lane = tid & 31;
    const int warp_m = wid & 1;    // 0..1, 64 rows each
    const int warp_n = wid >> 1;   // 0..3, 32 cols each
    const int bn = blockIdx.x * BN;
    const int bm = blockIdx.y * BM;

    uint32_t sA[STAGES], sB[STAGES];
    #pragma unroll
    for (int s = 0; s < STAGES; s++) {
        sA[s] = sb + s * STAGE_BYTES;
        sB[s] = sA[s] + 16384;
    }

    float acc[4][4][4];   // [mtile][ntile][reg], warp tile 64x32
    #pragma unroll
    for (int a = 0; a < 4; a++)
        #pragma unroll
        for (int b = 0; b < 4; b++)
            #pragma unroll
            for (int c = 0; c < 4; c++)
                acc[a][b][c] = 0.0f;

    #pragma unroll
    for (int s = 0; s < STAGES - 1; s++) {
        load_stage(sA[s], sB[s], bm, bn, s * BK, tid);
        CP_COMMIT();
    }

    for (int i = 0; i < NITER; i++) {
        CP_WAIT(STAGES - 2);
        __syncthreads();

        // prefetch stage i+STAGES-1 into buffer (i-1)%STAGES (consumed in iter i-1)
        int ld = i + STAGES - 1;
        if (ld < NITER)
            load_stage(sA[ld % STAGES], sB[ld % STAGES], bm, bn, ld * BK, tid);
        CP_COMMIT();   // unconditional: keeps wait_group accounting exact in the tail

        const uint32_t a_base = sA[i % STAGES];
        const uint32_t b_base = sB[i % STAGES];
        const int kch_lane = lane >> 4;        // 0/1: k-chunk selector within ldmatrix.x4
        const int row_lane = lane & 15;

        #pragma unroll
        for (int ks = 0; ks < 4; ks++) {       // 4 x k16 per stage
            uint32_t afr[4][4];
            #pragma unroll
            for (int mt = 0; mt < 4; mt++) {
                int row = warp_m * 64 + mt * 16 + row_lane;
                uint32_t off = SWZ128((uint32_t)(row * 128 + (ks * 2 + kch_lane) * 16));
                ldsm_x4(afr[mt], a_base + off);
            }
            uint32_t bfr[2][4];
            #pragma unroll
            for (int nb = 0; nb < 2; nb++) {
                int rowN = warp_n * 32 + nb * 16 + row_lane;
                uint32_t off = SWZ128((uint32_t)(rowN * 128 + (ks * 2 + kch_lane) * 16));
                ldsm_x4(bfr[nb], b_base + off);
            }
            #pragma unroll
            for (int mt = 0; mt < 4; mt++)
                #pragma unroll
                for (int nt = 0; nt < 4; nt++)
                    mma16816(acc[mt][nt], afr[mt],
                             bfr[nt >> 1][nt & 1], bfr[nt >> 1][(nt & 1) + 2]);
        }
    }

    // ---- epilogue: bias + direct fp32 stores (float2 per m16n8 fragment row) ----
    const int qrow = lane >> 2;          // 0..7
    const int qcol = 2 * (lane & 3);     // 0,2,4,6
    #pragma unroll
    for (int nt = 0; nt < 4; nt++) {
        int col = bn + warp_n * 32 + nt * 8 + qcol;
        float b0 = __ldg(bias + col);
        float b1 = __ldg(bias + col + 1);
        #pragma unroll
        for (int mt = 0; mt < 4; mt++) {
            int row = bm + warp_m * 64 + mt * 16 + qrow;
            float2 v0 = {acc[mt][nt][0] + b0, acc[mt][nt][1] + b1};
            float2 v1 = {acc[mt][nt][2] + b0, acc[mt][nt][3] + b1};
            *reinterpret_cast<float2*>(out + (size_t)row * N_DIM + col) = v0;
            *reinterpret_cast<float2*>(out + (size_t)(row + 8) * N_DIM + col) = v1;
        }
    }
}

// ---------------- launch ----------------
extern "C" void kernel_launch(void* const* d_in, const int* in_sizes, int n_in,
                              void* d_out, int out_size)
{
    const float* x      = (const float*)d_in[0];
    const int*   qw     = (const int*)  d_in[1];
    const float* scales = (const float*)d_in[2];
    const float* zeros  = (const float*)d_in[3];
    const float* bias   = (const float*)d_in[4];
    float* out          = (float*)d_out;

    cudaFuncSetAttribute(gemm_f16_kernel, cudaFuncAttributeMaxDynamicSharedMemorySize, SMEM_TOTAL);

    {
        size_t total = (size_t)N_DIM * (K_DIM / 8);
        dequant_w_kernel<<<(unsigned)((total + 255) / 256), 256>>>(qw, scales, zeros);
    }
    {
        size_t total = (size_t)M_DIM * K_DIM / 8;
        convert_x_kernel<<<(unsigned)((total + 255) / 256), 256>>>(x);
    }
    {
        dim3 grid(N_DIM / BN, M_DIM / BM);   // (86, 64)
        gemm_f16_kernel<<<grid, THREADS, SMEM_TOTAL>>>(bias, out);
    }
}

// round 5
// speedup vs baseline: 7.2950x; 1.0771x over previous
#include <cuda_runtime.h>
#include <cuda_fp16.h>
#include <cstdint>

// GPTQ int4 linear on GB300 via legacy tensor path (mma.sync, base sm_103 target):
//   Pass 1: dequant qweight -> fp16 W[N,K] (device global), convert x -> fp16.
//   Pass 2: 256x128x64 tiled fp16 GEMM, warp tile 64x64, mma.sync.m16n8k16,
//           ldmatrix, 3-stage cp.async pipeline.
// M=8192, N=11008, K=4096, GS=128.

#define M_DIM 8192
#define N_DIM 11008
#define K_DIM 4096
#define BM 256
#define BN 128
#define BK 64                 // halfs per stage (128 bytes per row, SW128)
#define STAGES 3
#define NITER (K_DIM / BK)    // 64
#define THREADS 256

__device__ __half g_Wh[(size_t)N_DIM * K_DIM];   // 90 MB
__device__ __half g_Xh[(size_t)M_DIM * K_DIM];   // 64 MB

#define SWZ128(o) ((o) ^ (((o) >> 3) & 0x70))

#define CP_ASYNC16(dst, src) \
    asm volatile("cp.async.cg.shared.global [%0], [%1], 16;" :: "r"(dst), "l"(src))
#define CP_COMMIT() asm volatile("cp.async.commit_group;" ::: "memory")
#define CP_WAIT(n)  asm volatile("cp.async.wait_group %0;" :: "n"(n) : "memory")

__device__ __forceinline__ uint32_t smem_u32(const void* p) {
    uint32_t a;
    asm("{ .reg .u64 t; cvta.to.shared.u64 t, %1; cvt.u32.u64 %0, t; }" : "=r"(a) : "l"(p));
    return a;
}
__device__ __forceinline__ void ldsm_x4(uint32_t* r, uint32_t addr) {
    asm volatile("ldmatrix.sync.aligned.m8n8.x4.shared.b16 {%0,%1,%2,%3}, [%4];"
                 : "=r"(r[0]), "=r"(r[1]), "=r"(r[2]), "=r"(r[3]) : "r"(addr));
}
__device__ __forceinline__ void mma16816(float* c, const uint32_t* a, uint32_t b0, uint32_t b1) {
    asm volatile("mma.sync.aligned.m16n8k16.row.col.f32.f16.f16.f32 "
                 "{%0,%1,%2,%3}, {%4,%5,%6,%7}, {%8,%9}, {%0,%1,%2,%3};"
                 : "+f"(c[0]), "+f"(c[1]), "+f"(c[2]), "+f"(c[3])
                 : "r"(a[0]), "r"(a[1]), "r"(a[2]), "r"(a[3]), "r"(b0), "r"(b1));
}

// ---------------- Pass 1: dequant W -> fp16 ----------------
__global__ void dequant_w_kernel(const int* __restrict__ qw,        // [N, K/2], one byte per int32
                                 const float* __restrict__ scales,  // [N, 32]
                                 const float* __restrict__ zeros)   // [N, 32]
{
    size_t t = (size_t)blockIdx.x * blockDim.x + threadIdx.x;   // 1 thread = 4 int32 = 8 weights
    const size_t total = (size_t)N_DIM * (K_DIM / 8);
    if (t >= total) return;
    int n  = (int)(t >> 9);           // K/8 = 512 per row
    int c4 = (int)(t & 511);
    int g  = c4 >> 4;                 // (c4*8)/128
    float sc = scales[(size_t)n * 32 + g];
    float zp = zeros [(size_t)n * 32 + g];
    int4 q = *reinterpret_cast<const int4*>(qw + (size_t)n * 2048 + c4 * 4);
    int qs[4] = {q.x, q.y, q.z, q.w};
    __half h[8];
    #pragma unroll
    for (int j = 0; j < 4; j++) {
        float lo = (float)(qs[j] & 15);
        float hi = (float)((qs[j] >> 4) & 15);
        h[2 * j    ] = __float2half_rn((lo - zp) * sc);
        h[2 * j + 1] = __float2half_rn((hi - zp) * sc);
    }
    *reinterpret_cast<uint4*>(&g_Wh[(size_t)n * K_DIM + (size_t)c4 * 8]) =
        *reinterpret_cast<const uint4*>(h);
}

// ---------------- Pass 1b: convert x -> fp16 ----------------
__global__ void convert_x_kernel(const float* __restrict__ x)
{
    size_t t = (size_t)blockIdx.x * blockDim.x + threadIdx.x;   // 1 thread = 8 floats
    const size_t total = (size_t)M_DIM * K_DIM / 8;
    if (t >= total) return;
    size_t base = t * 8;
    float4 a = *reinterpret_cast<const float4*>(x + base);
    float4 b = *reinterpret_cast<const float4*>(x + base + 4);
    __half h[8] = {__float2half_rn(a.x), __float2half_rn(a.y), __float2half_rn(a.z), __float2half_rn(a.w),
                   __float2half_rn(b.x), __float2half_rn(b.y), __float2half_rn(b.z), __float2half_rn(b.w)};
    *reinterpret_cast<uint4*>(&g_Xh[base]) = *reinterpret_cast<const uint4*>(h);
}

// ---------------- Pass 2: mma.sync fp16 GEMM ----------------
// SMEM per stage: A 256x64 fp16 (32KB) + B 128x64 fp16 (16KB) = 48KB. 3 stages = 144KB.
#define A_BYTES 32768
#define STAGE_BYTES 49152
#define SMEM_TOTAL (STAGES * STAGE_BYTES)

__device__ __forceinline__ void load_stage(uint32_t sA, uint32_t sB,
                                           int bm, int bn, int k0, int tid)
{
    // A: 2048 16B-chunks, 8 per thread. B: 1024 chunks, 4 per thread.
    #pragma unroll
    for (int j = 0; j < 8; j++) {
        int chunk = tid + j * THREADS;
        int row = chunk >> 3, c16 = chunk & 7;
        uint32_t off = SWZ128((uint32_t)(row * 128 + c16 * 16));
        CP_ASYNC16(sA + off, g_Xh + (size_t)(bm + row) * K_DIM + k0 + c16 * 8);
    }
    #pragma unroll
    for (int j = 0; j < 4; j++) {
        int chunk = tid + j * THREADS;
        int row = chunk >> 3, c16 = chunk & 7;
        uint32_t off = SWZ128((uint32_t)(row * 128 + c16 * 16));
        CP_ASYNC16(sB + off, g_Wh + (size_t)(bn + row) * K_DIM + k0 + c16 * 8);
    }
}

__global__ __launch_bounds__(THREADS, 1)
void gemm_f16_kernel(const float* __restrict__ bias, float* __restrict__ out)
{
    extern __shared__ char smem[];
    const uint32_t sb = smem_u32(smem);
    const int tid = threadIdx.x;
    const int wid = tid >> 5, lane = tid & 31;
    const int warp_m = wid & 3;    // 0..3, 64 rows each
    const int warp_n = wid >> 2;   // 0..1, 64 cols each
    const int bn = blockIdx.x * BN;
    const int bm = blockIdx.y * BM;

    uint32_t sA[STAGES], sB[STAGES];
    #pragma unroll
    for (int s = 0; s < STAGES; s++) {
        sA[s] = sb + s * STAGE_BYTES;
        sB[s] = sA[s] + A_BYTES;
    }

    float acc[4][8][4];   // warp tile 64x64: [m16 tile][n8 tile][reg]
    #pragma unroll
    for (int a = 0; a < 4; a++)
        #pragma unroll
        for (int b = 0; b < 8; b++)
            #pragma unroll
            for (int c = 0; c < 4; c++)
                acc[a][b][c] = 0.0f;

    #pragma unroll
    for (int s = 0; s < STAGES - 1; s++) {
        load_stage(sA[s], sB[s], bm, bn, s * BK, tid);
        CP_COMMIT();
    }

    const int kch_lane = lane >> 4;        // 0/1: k-chunk selector within ldmatrix.x4
    const int row_lane = lane & 15;

    for (int i = 0; i < NITER; i++) {
        CP_WAIT(STAGES - 2);
        __syncthreads();

        int ld = i + STAGES - 1;
        if (ld < NITER)
            load_stage(sA[ld % STAGES], sB[ld % STAGES], bm, bn, ld * BK, tid);
        CP_COMMIT();   // unconditional: keeps wait_group accounting exact in the tail

        const uint32_t a_base = sA[i % STAGES];
        const uint32_t b_base = sB[i % STAGES];

        #pragma unroll
        for (int ks = 0; ks < 4; ks++) {       // 4 x k16 per stage
            uint32_t afr[4][4];
            #pragma unroll
            for (int mt = 0; mt < 4; mt++) {
                int row = warp_m * 64 + mt * 16 + row_lane;
                uint32_t off = SWZ128((uint32_t)(row * 128 + (ks * 2 + kch_lane) * 16));
                ldsm_x4(afr[mt], a_base + off);
            }
            uint32_t bfr[4][4];
            #pragma unroll
            for (int nb = 0; nb < 4; nb++) {
                int rowN = warp_n * 64 + nb * 16 + row_lane;
                uint32_t off = SWZ128((uint32_t)(rowN * 128 + (ks * 2 + kch_lane) * 16));
                ldsm_x4(bfr[nb], b_base + off);
            }
            #pragma unroll
            for (int mt = 0; mt < 4; mt++)
                #pragma unroll
                for (int nt = 0; nt < 8; nt++)
                    mma16816(acc[mt][nt], afr[mt],
                             bfr[nt >> 1][nt & 1], bfr[nt >> 1][(nt & 1) + 2]);
        }
    }

    // ---- epilogue: bias + direct fp32 stores (float2 per m16n8 fragment row) ----
    const int qrow = lane >> 2;          // 0..7
    const int qcol = 2 * (lane & 3);     // 0,2,4,6
    #pragma unroll
    for (int nt = 0; nt < 8; nt++) {
        int col = bn + warp_n * 64 + nt * 8 + qcol;
        float b0 = __ldg(bias + col);
        float b1 = __ldg(bias + col + 1);
        #pragma unroll
        for (int mt = 0; mt < 4; mt++) {
            int row = bm + warp_m * 64 + mt * 16 + qrow;
            float2 v0 = {acc[mt][nt][0] + b0, acc[mt][nt][1] + b1};
            float2 v1 = {acc[mt][nt][2] + b0, acc[mt][nt][3] + b1};
            *reinterpret_cast<float2*>(out + (size_t)row * N_DIM + col) = v0;
            *reinterpret_cast<float2*>(out + (size_t)(row + 8) * N_DIM + col) = v1;
        }
    }
}

// ---------------- launch ----------------
extern "C" void kernel_launch(void* const* d_in, const int* in_sizes, int n_in,
                              void* d_out, int out_size)
{
    const float* x      = (const float*)d_in[0];
    const int*   qw     = (const int*)  d_in[1];
    const float* scales = (const float*)d_in[2];
    const float* zeros  = (const float*)d_in[3];
    const float* bias   = (const float*)d_in[4];
    float* out          = (float*)d_out;

    cudaFuncSetAttribute(gemm_f16_kernel, cudaFuncAttributeMaxDynamicSharedMemorySize, SMEM_TOTAL);

    {
        size_t total = (size_t)N_DIM * (K_DIM / 8);
        dequant_w_kernel<<<(unsigned)((total + 255) / 256), 256>>>(qw, scales, zeros);
    }
    {
        size_t total = (size_t)M_DIM * K_DIM / 8;
        convert_x_kernel<<<(unsigned)((total + 255) / 256), 256>>>(x);
    }
    {
        dim3 grid(N_DIM / BN, M_DIM / BM);   // (86, 32)
        gemm_f16_kernel<<<grid, THREADS, SMEM_TOTAL>>>(bias, out);
    }
}